// round 14
// baseline (speedup 1.0000x reference)
#include <cuda_runtime.h>
#include <cuda_bf16.h>
#include <math_constants.h>
#include <math.h>
#include <cstdint>

#define BATCH 2
#define SEQ   2048
#define HID   4096
#define NH    32
#define HDIM  128
#define QKVN  (3*HID)
#define MROWS (BATCH*SEQ)      // 4096
#define KSPLIT (3*HID)         // 12288 : 3-term split-concatenated K

// ---------------- scratch (device globals: allocation-guard safe) ----------
__device__ float         g_qkv[(size_t)MROWS * QKVN];     // only v third is used now
__device__ __nv_bfloat16 g_A2 [(size_t)MROWS * KSPLIT];   // [Ahi|Ahi|Alo]
__device__ __nv_bfloat16 g_B2 [(size_t)QKVN  * KSPLIT];   // [Bhi|Blo|Bhi] (N-major)
// flash operands: [bh][s][d] for q,k ; [bh][d][s] for v (transposed)
__device__ __nv_bfloat16 g_qhi[(size_t)BATCH * NH * SEQ * HDIM];
__device__ __nv_bfloat16 g_qlo[(size_t)BATCH * NH * SEQ * HDIM];
__device__ __nv_bfloat16 g_khi[(size_t)BATCH * NH * SEQ * HDIM];
__device__ __nv_bfloat16 g_klo[(size_t)BATCH * NH * SEQ * HDIM];
__device__ __nv_bfloat16 g_vhi[(size_t)BATCH * NH * SEQ * HDIM];
__device__ __nv_bfloat16 g_vlo[(size_t)BATCH * NH * SEQ * HDIM];
__device__ float2        g_rope[(size_t)MROWS * 32];      // (cos,sin) per (bs, j)

#define QSC (0.08838834764831845f * 1.4426950408889634f)  // 1/sqrt(128)*log2(e)

// ---------------- PTX helpers (sm_80-era, compute_103-safe) ----------------
__device__ __forceinline__ uint32_t smem_u32(const void* p) {
    uint32_t a;
    asm("{ .reg .u64 t; cvta.to.shared.u64 t, %1; cvt.u32.u64 %0, t; }" : "=r"(a) : "l"(p));
    return a;
}
__device__ __forceinline__ void cp16(uint32_t s, const void* g) {
    asm volatile("cp.async.cg.shared.global [%0], [%1], 16;" :: "r"(s), "l"(g) : "memory");
}
__device__ __forceinline__ void ldsm4(uint32_t* r, uint32_t addr) {
    asm volatile("ldmatrix.sync.aligned.m8n8.x4.shared.b16 {%0,%1,%2,%3}, [%4];"
                 : "=r"(r[0]), "=r"(r[1]), "=r"(r[2]), "=r"(r[3]) : "r"(addr));
}
__device__ __forceinline__ void mma_bf16(float* d, const uint32_t* a, uint32_t b0, uint32_t b1) {
    asm volatile("mma.sync.aligned.m16n8k16.row.col.f32.bf16.bf16.f32 "
                 "{%0,%1,%2,%3}, {%4,%5,%6,%7}, {%8,%9}, {%0,%1,%2,%3};"
                 : "+f"(d[0]), "+f"(d[1]), "+f"(d[2]), "+f"(d[3])
                 : "r"(a[0]), "r"(a[1]), "r"(a[2]), "r"(a[3]), "r"(b0), "r"(b1));
}
// pack: first arg -> low 16 bits (lower address), second -> high
__device__ __forceinline__ uint32_t pack_bf16(float lo, float hi) {
    uint32_t r;
    asm("cvt.rn.bf16x2.f32 %0, %1, %2;" : "=r"(r) : "f"(hi), "f"(lo));
    return r;
}
// fast 2^t on FMA pipe (no MUFU); t clamped at -120
__device__ __forceinline__ float exp2p(float t) {
    t = fmaxf(t, -120.f);
    float n = floorf(t);
    float f = t - n;
    float p = fmaf(f, 1.3333558e-4f, 1.3400431e-3f);
    p = fmaf(f, p, 9.6181291e-3f);
    p = fmaf(f, p, 5.5504109e-2f);
    p = fmaf(f, p, 2.4022651e-1f);
    p = fmaf(f, p, 6.9314718e-1f);
    p = fmaf(f, p, 1.0f);
    return p * __int_as_float(((int)n + 127) << 23);
}

struct alignas(8) bh4 { __nv_bfloat16 h[4]; };

// ============================================================================
// Split prepass 1: activations  src fp32 [M][4096] -> A2 bf16 [M][12288]
// ============================================================================
__global__ __launch_bounds__(256) void split_act_kernel(const float* __restrict__ src,
                                                        __nv_bfloat16* __restrict__ dst) {
    size_t i = (size_t)blockIdx.x * 256 + threadIdx.x;
    int row = (int)(i >> 10);
    int kc  = (int)(i & 1023);
    float4 v = ((const float4*)src)[i];
    bh4 hi, lo;
    hi.h[0] = __float2bfloat16(v.x); lo.h[0] = __float2bfloat16(v.x - __bfloat162float(hi.h[0]));
    hi.h[1] = __float2bfloat16(v.y); lo.h[1] = __float2bfloat16(v.y - __bfloat162float(hi.h[1]));
    hi.h[2] = __float2bfloat16(v.z); lo.h[2] = __float2bfloat16(v.z - __bfloat162float(hi.h[2]));
    hi.h[3] = __float2bfloat16(v.w); lo.h[3] = __float2bfloat16(v.w - __bfloat162float(hi.h[3]));
    __nv_bfloat16* d = dst + (size_t)row * KSPLIT + kc * 4;
    *(bh4*)(d)        = hi;
    *(bh4*)(d + 4096) = hi;
    *(bh4*)(d + 8192) = lo;
}

// ============================================================================
// Split prepass 2: weights  src fp32 [K=4096][N] -> B2 bf16 [N][12288]
// ============================================================================
__global__ __launch_bounds__(256) void split_w_kernel(const float* __restrict__ src,
                                                      __nv_bfloat16* __restrict__ dst,
                                                      int N) {
    __shared__ float t[32][33];
    int n0 = blockIdx.x * 32, k0 = blockIdx.y * 32;
    int tx = threadIdx.x & 31, ty = threadIdx.x >> 5;
#pragma unroll
    for (int i = 0; i < 4; i++)
        t[ty + i * 8][tx] = src[(size_t)(k0 + ty + i * 8) * N + n0 + tx];
    __syncthreads();
#pragma unroll
    for (int i = 0; i < 4; i++) {
        int n = n0 + ty + i * 8;
        int k = k0 + tx;
        float x = t[tx][ty + i * 8];
        __nv_bfloat16 hi = __float2bfloat16(x);
        __nv_bfloat16 lo = __float2bfloat16(x - __bfloat162float(hi));
        __nv_bfloat16* d = dst + (size_t)n * KSPLIT;
        d[k]        = hi;
        d[4096 + k] = lo;
        d[8192 + k] = hi;
    }
}

// ============================================================================
// RoPE table: g_rope[bs][j] = (cos, sin) of positions[bs] * theta^(-j/32)
// ============================================================================
__global__ __launch_bounds__(256) void rope_tab_kernel(const int* __restrict__ positions) {
    int i  = blockIdx.x * 256 + threadIdx.x;   // over MROWS*32
    int bs = i >> 5, j = i & 31;
    float pos = (float)positions[bs];
    float inv = powf(10000.0f, -(float)j * (1.0f / 32.0f));
    float sn, cs;
    sincosf(pos * inv, &sn, &cs);
    g_rope[i] = make_float2(cs, sn);
}

// ============================================================================
// bf16 tensor-core GEMM: R10/R12 pipeline, PERSISTENT grid (296 CTAs).
// mode 1 = fused RoPE + q/k split epilogue (QKV projection).
// ============================================================================
#define GSTAGES   4
#define GROW_B    80
#define GTILE_B   (128 * GROW_B)
#define GSTAGE_B  (2 * GTILE_B)
#define GSMEM_B   (GSTAGES * GSTAGE_B)      // 81920

__global__ __launch_bounds__(128, 2) void gemm_bf16_kernel(const __nv_bfloat16* __restrict__ A,
                                                           const __nv_bfloat16* __restrict__ B,
                                                           float* __restrict__ C, int N,
                                                           int mode) {
    extern __shared__ char sm[];
    const int KT  = KSPLIT;
    const int NT  = KT / 32;                 // 384
    const int tid  = threadIdx.x;
    const int lane = tid & 31;
    const int wid  = tid >> 5;
    const int wm   = wid & 1;
    const int wn   = wid >> 1;

    const int tiles_n = N >> 7;
    const int total_tiles = tiles_n * (MROWS / 128);
    const uint32_t smb = smem_u32(sm);

    const int a_row = lane & 15;
    const int a_col = (lane >> 4) * 8;
    const int b_nl  = (lane & 7) + ((lane >> 4) & 1) * 8;
    const int b_kl  = ((lane >> 3) & 1) * 8;

    for (int t = blockIdx.x; t < total_tiles; t += gridDim.x) {
        int band = t / (8 * tiles_n);
        int rem  = t % (8 * tiles_n);
        const int mt = band * 8 + (rem & 7);
        const int nt = rem >> 3;
        const int row0 = mt * 128, col0 = nt * 128;

        const __nv_bfloat16* Ab = A + (size_t)row0 * KT;
        const __nv_bfloat16* Bb = B + (size_t)col0 * KT;

        auto load_stage = [&](int s, int kt) {
            uint32_t sA = smb + s * GSTAGE_B;
            const __nv_bfloat16* ga = Ab + kt * 32;
            const __nv_bfloat16* gb = Bb + kt * 32;
#pragma unroll
            for (int i = 0; i < 4; i++) {
                int c   = tid + i * 128;
                int row = c >> 2;
                int kc  = c & 3;
                cp16(sA + row * GROW_B + kc * 16,           ga + (size_t)row * KT + kc * 8);
                cp16(sA + GTILE_B + row * GROW_B + kc * 16, gb + (size_t)row * KT + kc * 8);
            }
        };

        auto ldsm_half = [&](uint32_t af[4][4], uint32_t bf[4][4], int s, int ks) {
            const uint32_t aB = smb + s * GSTAGE_B;
            const uint32_t bB = aB + GTILE_B;
#pragma unroll
            for (int mf = 0; mf < 4; mf++)
                ldsm4(af[mf], aB + (uint32_t)((wm * 64 + mf * 16 + a_row) * GROW_B
                                              + (ks * 16 + a_col) * 2));
#pragma unroll
            for (int nf2 = 0; nf2 < 4; nf2++)
                ldsm4(bf[nf2], bB + (uint32_t)((wn * 64 + nf2 * 16 + b_nl) * GROW_B
                                               + (ks * 16 + b_kl) * 2));
        };

        float acc[4][8][4];
#pragma unroll
        for (int i = 0; i < 4; i++)
#pragma unroll
            for (int j = 0; j < 8; j++)
#pragma unroll
                for (int q = 0; q < 4; q++) acc[i][j][q] = 0.f;

        auto mma_half = [&](uint32_t af[4][4], uint32_t bf[4][4]) {
#pragma unroll
            for (int nf2 = 0; nf2 < 4; nf2++)
#pragma unroll
                for (int mf = 0; mf < 4; mf++) {
                    mma_bf16(acc[mf][nf2 * 2],     af[mf], bf[nf2][0], bf[nf2][1]);
                    mma_bf16(acc[mf][nf2 * 2 + 1], af[mf], bf[nf2][2], bf[nf2][3]);
                }
        };

        load_stage(0, 0); asm volatile("cp.async.commit_group;" ::: "memory");
        load_stage(1, 1); asm volatile("cp.async.commit_group;" ::: "memory");
        load_stage(2, 2); asm volatile("cp.async.commit_group;" ::: "memory");

        uint32_t af0[4][4], bf0[4][4], af1[4][4], bf1[4][4];

        asm volatile("cp.async.wait_group 2;" ::: "memory");
        __syncthreads();
        ldsm_half(af0, bf0, 0, 0);

        for (int kt = 0; kt < NT; kt++) {
            const int s = kt & 3;

            ldsm_half(af1, bf1, s, 1);
            mma_half(af0, bf0);

            if (kt + 3 < NT) load_stage((kt + 3) & 3, kt + 3);
            asm volatile("cp.async.commit_group;" ::: "memory");

            if (kt + 1 < NT) {
                asm volatile("cp.async.wait_group 2;" ::: "memory");
                __syncthreads();
                ldsm_half(af0, bf0, (kt + 1) & 3, 0);
            }
            mma_half(af1, bf1);
        }

        // ---------------------------- epilogue ----------------------------
        // (after the final in-tile sync only stage 3 is read; next tile's
        //  prologue writes stages 0-2 — disjoint, no extra barrier needed)
        const int sec = col0 >> 12;
        if (mode == 0 || sec == 2) {
#pragma unroll
            for (int mf = 0; mf < 4; mf++)
#pragma unroll
                for (int nf = 0; nf < 8; nf++) {
                    int r  = row0 + wm * 64 + mf * 16 + (lane >> 2);
                    int cc = col0 + wn * 64 + nf * 8 + (lane & 3) * 2;
                    *(float2*)&C[(size_t)r * N + cc]       = make_float2(acc[mf][nf][0], acc[mf][nf][1]);
                    *(float2*)&C[(size_t)(r + 8) * N + cc] = make_float2(acc[mf][nf][2], acc[mf][nf][3]);
                }
        } else {
            const int h   = (col0 & 4095) >> 7;
            const bool rot = (wn == 0);
            __nv_bfloat16* dhi = (sec == 0) ? g_qhi : g_khi;
            __nv_bfloat16* dlo = (sec == 0) ? g_qlo : g_klo;
            const float scl = (sec == 0) ? QSC : 1.0f;
#pragma unroll
            for (int mf = 0; mf < 4; mf++)
#pragma unroll
                for (int rr = 0; rr < 2; rr++) {
                    int r  = row0 + wm * 64 + mf * 16 + (lane >> 2) + rr * 8;
                    int bb = r >> 11, ss = r & 2047;
                    float vals[8][2];
#pragma unroll
                    for (int nf = 0; nf < 8; nf++) {
                        vals[nf][0] = acc[mf][nf][rr * 2 + 0];
                        vals[nf][1] = acc[mf][nf][rr * 2 + 1];
                    }
                    if (rot) {
#pragma unroll
                        for (int nf = 0; nf < 4; nf++)
#pragma unroll
                            for (int q = 0; q < 2; q++) {
                                int j = nf * 8 + (lane & 3) * 2 + q;
                                float2 tt = g_rope[(size_t)r * 32 + j];
                                float x1 = vals[nf][q], x2 = vals[nf + 4][q];
                                vals[nf][q]     = x1 * tt.x - x2 * tt.y;
                                vals[nf + 4][q] = x2 * tt.x + x1 * tt.y;
                            }
                    }
                    size_t base = ((size_t)(bb * NH + h) * SEQ + ss) * HDIM
                                  + wn * 64 + (lane & 3) * 2;
#pragma unroll
                    for (int nf = 0; nf < 8; nf++) {
                        float x0 = vals[nf][0] * scl;
                        float x1 = vals[nf][1] * scl;
                        float h0 = __bfloat162float(__float2bfloat16(x0));
                        float h1 = __bfloat162float(__float2bfloat16(x1));
                        *(uint32_t*)&dhi[base + nf * 8] = pack_bf16(x0, x1);
                        *(uint32_t*)&dlo[base + nf * 8] = pack_bf16(x0 - h0, x1 - h1);
                    }
                }
        }
    }
}

// ============================================================================
// Flash prepass B: split v to bf16 hi/lo TRANSPOSED, layout [bh][d][s]
// ============================================================================
__global__ __launch_bounds__(256) void split_v_kernel() {
    __shared__ float t[32][33];
    int s0 = blockIdx.x * 32;
    int d0 = blockIdx.y * 32;
    int bh = blockIdx.z;
    int b  = bh >> 5, h = bh & 31;
    int tx = threadIdx.x & 31, ty = threadIdx.x >> 5;
#pragma unroll
    for (int i = 0; i < 4; i++)
        t[ty + i * 8][tx] = g_qkv[((size_t)(b * SEQ + s0 + ty + i * 8)) * QKVN
                                  + 2 * HID + h * HDIM + d0 + tx];
    __syncthreads();
#pragma unroll
    for (int i = 0; i < 4; i++) {
        int d = d0 + ty + i * 8;
        float x = t[tx][ty + i * 8];
        __nv_bfloat16 hi = __float2bfloat16(x);
        __nv_bfloat16 lo = __float2bfloat16(x - __bfloat162float(hi));
        size_t dst = ((size_t)bh * HDIM + d) * SEQ + s0 + tx;
        g_vhi[dst] = hi;
        g_vlo[dst] = lo;
    }
}

// ============================================================================
// Tensor-core flash attention (bf16 hi/lo 3-term), causal.
// Deferred l-reduction (alpha uniform within quad); Q fragments from smem.
// Epilogue writes bf16 3-term A-operand [Ahi|Ahi|Alo] for the out-projection.
// ============================================================================
#define FQ   128
#define FK   64
#define QROWB 272
#define VROWB 144
#define OQH  0
#define OQL  34816
#define OST  69632
#define FKL  17408
#define FVH  34816
#define FVL  53248
#define FSTAGE 71680
#define FSMEM (OST + 2 * FSTAGE)   // 212992

__global__ __launch_bounds__(256, 1) void flash_tc_kernel() {
    extern __shared__ char sm[];
    const uint32_t smb = smem_u32(sm);
    const int tid  = threadIdx.x;
    const int lane = tid & 31;
    const int w    = tid >> 5;
    const int qt   = gridDim.x - 1 - blockIdx.x;
    const int bh   = blockIdx.y;
    const int ntiles = 2 * qt + 2;

    {
        size_t qoff = ((size_t)bh * SEQ + (size_t)qt * FQ) * HDIM;
#pragma unroll
        for (int i = tid; i < 2048; i += 256) {
            int r = i >> 4, c = i & 15;
            cp16(smb + OQH + r * QROWB + c * 16, g_qhi + qoff + (size_t)r * HDIM + c * 8);
            cp16(smb + OQL + r * QROWB + c * 16, g_qlo + qoff + (size_t)r * HDIM + c * 8);
        }
    }

    auto load_kv = [&](int st, int kt) {
        uint32_t sb = smb + OST + st * FSTAGE;
        size_t koff = ((size_t)bh * SEQ + (size_t)kt * FK) * HDIM;
#pragma unroll
        for (int i = tid; i < 1024; i += 256) {
            int r = i >> 4, c = i & 15;
            cp16(sb + r * QROWB + c * 16,       g_khi + koff + (size_t)r * HDIM + c * 8);
            cp16(sb + FKL + r * QROWB + c * 16, g_klo + koff + (size_t)r * HDIM + c * 8);
        }
        size_t voff = (size_t)bh * HDIM * SEQ + (size_t)kt * FK;
#pragma unroll
        for (int i = tid; i < 1024; i += 256) {
            int d = i >> 3, c = i & 7;
            cp16(sb + FVH + d * VROWB + c * 16, g_vhi + voff + (size_t)d * SEQ + c * 8);
            cp16(sb + FVL + d * VROWB + c * 16, g_vlo + voff + (size_t)d * SEQ + c * 8);
        }
    };

    load_kv(0, 0);
    asm volatile("cp.async.commit_group;" ::: "memory");

    float o[16][4];
#pragma unroll
    for (int i = 0; i < 16; i++)
#pragma unroll
        for (int j = 0; j < 4; j++) o[i][j] = 0.f;
    float m0 = -CUDART_INF_F, m1 = -CUDART_INF_F, l0 = 0.f, l1 = 0.f;

    const int a_row = lane & 15;
    const int a_col = (lane >> 4) * 8;
    const int b_nl  = (lane & 7) + ((lane >> 4) & 1) * 8;
    const int b_kl  = ((lane >> 3) & 1) * 8;
    const int qrow0 = qt * FQ + w * 16 + (lane >> 2);

    for (int kt = 0; kt < ntiles; kt++) {
        if (kt + 1 < ntiles) load_kv((kt + 1) & 1, kt + 1);
        asm volatile("cp.async.commit_group;" ::: "memory");
        asm volatile("cp.async.wait_group 1;" ::: "memory");
        __syncthreads();

        const uint32_t kb = smb + OST + (kt & 1) * FSTAGE;
        const uint32_t vb = kb + FVH;

        float s[8][4];
#pragma unroll
        for (int i = 0; i < 8; i++)
#pragma unroll
            for (int j = 0; j < 4; j++) s[i][j] = 0.f;

#pragma unroll
        for (int ks = 0; ks < 8; ks++) {
            uint32_t qh[4], ql[4];
            uint32_t qaddr = smb + OQH + (uint32_t)((w * 16 + a_row) * QROWB + (ks * 16 + a_col) * 2);
            ldsm4(qh, qaddr);
            ldsm4(ql, qaddr + (OQL - OQH));
#pragma unroll
            for (int nt2 = 0; nt2 < 4; nt2++) {
                uint32_t kh[4], kl[4];
                uint32_t kaddr = kb + (uint32_t)((nt2 * 16 + b_nl) * QROWB + (ks * 16 + b_kl) * 2);
                ldsm4(kh, kaddr);
                ldsm4(kl, kaddr + FKL);
                mma_bf16(s[nt2 * 2],     qh, kh[0], kh[1]);
                mma_bf16(s[nt2 * 2 + 1], qh, kh[2], kh[3]);
                mma_bf16(s[nt2 * 2],     qh, kl[0], kl[1]);
                mma_bf16(s[nt2 * 2 + 1], qh, kl[2], kl[3]);
                mma_bf16(s[nt2 * 2],     ql, kh[0], kh[1]);
                mma_bf16(s[nt2 * 2 + 1], ql, kh[2], kh[3]);
            }
        }

        if (kt * FK + FK - 1 > qt * FQ + w * 16) {
#pragma unroll
            for (int nt = 0; nt < 8; nt++) {
                int key = kt * FK + nt * 8 + (lane & 3) * 2;
                if (key     > qrow0)     s[nt][0] = -CUDART_INF_F;
                if (key + 1 > qrow0)     s[nt][1] = -CUDART_INF_F;
                if (key     > qrow0 + 8) s[nt][2] = -CUDART_INF_F;
                if (key + 1 > qrow0 + 8) s[nt][3] = -CUDART_INF_F;
            }
        }

        float mx0 = -CUDART_INF_F, mx1 = -CUDART_INF_F;
#pragma unroll
        for (int nt = 0; nt < 8; nt++) {
            mx0 = fmaxf(mx0, fmaxf(s[nt][0], s[nt][1]));
            mx1 = fmaxf(mx1, fmaxf(s[nt][2], s[nt][3]));
        }
        mx0 = fmaxf(mx0, __shfl_xor_sync(0xffffffffu, mx0, 1));
        mx0 = fmaxf(mx0, __shfl_xor_sync(0xffffffffu, mx0, 2));
        mx1 = fmaxf(mx1, __shfl_xor_sync(0xffffffffu, mx1, 1));
        mx1 = fmaxf(mx1, __shfl_xor_sync(0xffffffffu, mx1, 2));
        float mn0 = fmaxf(m0, mx0), mn1 = fmaxf(m1, mx1);
        float al0 = exp2p(m0 - mn0), al1 = exp2p(m1 - mn1);
        m0 = mn0; m1 = mn1;

        float sum0 = 0.f, sum1 = 0.f;
#pragma unroll
        for (int nt = 0; nt < 8; nt++) {
            s[nt][0] = exp2p(s[nt][0] - mn0); sum0 += s[nt][0];
            s[nt][1] = exp2p(s[nt][1] - mn0); sum0 += s[nt][1];
            s[nt][2] = exp2p(s[nt][2] - mn1); sum1 += s[nt][2];
            s[nt][3] = exp2p(s[nt][3] - mn1); sum1 += s[nt][3];
        }
        // deferred l-reduction: keep per-thread quarter-row partials
        l0 = l0 * al0 + sum0;
        l1 = l1 * al1 + sum1;

#pragma unroll
        for (int nt = 0; nt < 16; nt++) {
            o[nt][0] *= al0; o[nt][1] *= al0;
            o[nt][2] *= al1; o[nt][3] *= al1;
        }

#pragma unroll
        for (int g = 0; g < 4; g++) {
            float h00 = __bfloat162float(__float2bfloat16(s[2*g][0]));
            float h01 = __bfloat162float(__float2bfloat16(s[2*g][1]));
            float h02 = __bfloat162float(__float2bfloat16(s[2*g][2]));
            float h03 = __bfloat162float(__float2bfloat16(s[2*g][3]));
            float h10 = __bfloat162float(__float2bfloat16(s[2*g+1][0]));
            float h11 = __bfloat162float(__float2bfloat16(s[2*g+1][1]));
            float h12 = __bfloat162float(__float2bfloat16(s[2*g+1][2]));
            float h13 = __bfloat162float(__float2bfloat16(s[2*g+1][3]));
            uint32_t phi[4], plo[4];
            phi[0] = pack_bf16(h00, h01);
            phi[1] = pack_bf16(h02, h03);
            phi[2] = pack_bf16(h10, h11);
            phi[3] = pack_bf16(h12, h13);
            plo[0] = pack_bf16(s[2*g][0] - h00,   s[2*g][1] - h01);
            plo[1] = pack_bf16(s[2*g][2] - h02,   s[2*g][3] - h03);
            plo[2] = pack_bf16(s[2*g+1][0] - h10, s[2*g+1][1] - h11);
            plo[3] = pack_bf16(s[2*g+1][2] - h12, s[2*g+1][3] - h13);

#pragma unroll
            for (int dt2 = 0; dt2 < 8; dt2++) {
                uint32_t vh[4], vl[4];
                uint32_t vaddr = vb + (uint32_t)((dt2 * 16 + b_nl) * VROWB + (g * 16 + b_kl) * 2);
                ldsm4(vh, vaddr);
                ldsm4(vl, vaddr + (FVL - FVH));
                mma_bf16(o[dt2 * 2],     phi, vh[0], vh[1]);
                mma_bf16(o[dt2 * 2 + 1], phi, vh[2], vh[3]);
                mma_bf16(o[dt2 * 2],     phi, vl[0], vl[1]);
                mma_bf16(o[dt2 * 2 + 1], phi, vl[2], vl[3]);
                mma_bf16(o[dt2 * 2],     plo, vh[0], vh[1]);
                mma_bf16(o[dt2 * 2 + 1], plo, vh[2], vh[3]);
            }
        }
        __syncthreads();
    }

    // ---- deferred cross-thread l reduction (alpha uniform within quad) ----
    l0 += __shfl_xor_sync(0xffffffffu, l0, 1);
    l0 += __shfl_xor_sync(0xffffffffu, l0, 2);
    l1 += __shfl_xor_sync(0xffffffffu, l1, 1);
    l1 += __shfl_xor_sync(0xffffffffu, l1, 2);

    // ---- epilogue: write bf16 [Ahi|Ahi|Alo] A-operand rows into g_A2 ----
    const float invl0 = 1.0f / l0;
    const float invl1 = 1.0f / l1;
    const int b = bh >> 5, h = bh & 31;
    const size_t r0 = (size_t)(b * SEQ + qt * FQ + w * 16 + (lane >> 2));
#pragma unroll
    for (int nt = 0; nt < 16; nt++) {
        size_t cbase = (size_t)h * HDIM + nt * 8 + (lane & 3) * 2;
        float x0 = o[nt][0] * invl0, x1 = o[nt][1] * invl0;
        float x2 = o[nt][2] * invl1, x3 = o[nt][3] * invl1;

        float h0 = __bfloat162float(__float2bfloat16(x0));
        float h1 = __bfloat162float(__float2bfloat16(x1));
        float h2 = __bfloat162float(__float2bfloat16(x2));
        float h3 = __bfloat162float(__float2bfloat16(x3));
        uint32_t hi01 = pack_bf16(x0, x1);
        uint32_t lo01 = pack_bf16(x0 - h0, x1 - h1);
        uint32_t hi23 = pack_bf16(x2, x3);
        uint32_t lo23 = pack_bf16(x2 - h2, x3 - h3);

        __nv_bfloat16* a0 = &g_A2[r0 * KSPLIT + cbase];
        __nv_bfloat16* a1 = &g_A2[(r0 + 8) * KSPLIT + cbase];
        *(uint32_t*)(a0)        = hi01;
        *(uint32_t*)(a0 + 4096) = hi01;
        *(uint32_t*)(a0 + 8192) = lo01;
        *(uint32_t*)(a1)        = hi23;
        *(uint32_t*)(a1 + 4096) = hi23;
        *(uint32_t*)(a1 + 8192) = lo23;
    }
}

// ============================================================================
extern "C" void kernel_launch(void* const* d_in, const int* in_sizes, int n_in,
                              void* d_out, int out_size) {
    const float* hidden    = (const float*)d_in[0];
    const int*   positions = (const int*)d_in[1];
    const float* Wqkv      = (const float*)d_in[2];
    const float* Wout      = (const float*)d_in[3];
    float*       out       = (float*)d_out;

    float*         qkv; cudaGetSymbolAddress((void**)&qkv, g_qkv);
    __nv_bfloat16* A2;  cudaGetSymbolAddress((void**)&A2,  g_A2);
    __nv_bfloat16* B2;  cudaGetSymbolAddress((void**)&B2,  g_B2);

    static bool attr_done = false;
    if (!attr_done) {
        cudaFuncSetAttribute(gemm_bf16_kernel, cudaFuncAttributeMaxDynamicSharedMemorySize, GSMEM_B);
        cudaFuncSetAttribute(flash_tc_kernel, cudaFuncAttributeMaxDynamicSharedMemorySize, FSMEM);
        attr_done = true;
    }

    // 1) split hidden -> A2, Wqkv -> B2 (bf16 3-term) ; rope table
    split_act_kernel<<<(MROWS * (HID / 4)) / 256, 256>>>(hidden, A2);
    split_w_kernel<<<dim3(QKVN / 32, HID / 32), 256>>>(Wqkv, B2, QKVN);
    rope_tab_kernel<<<(MROWS * 32) / 256, 256>>>(positions);

    // 2) QKV projection, persistent grid, fused rope+split epilogue (mode 1)
    gemm_bf16_kernel<<<296, 128, GSMEM_B>>>(A2, B2, qkv, QKVN, 1);

    // 3) split v (transposed)
    split_v_kernel<<<dim3(SEQ / 32, HDIM / 32, BATCH * NH), 256>>>();

    // 4) tensor-core causal flash attention (writes A2 for out-proj)
    flash_tc_kernel<<<dim3(SEQ / FQ, BATCH * NH), 256, FSMEM>>>();

    // 5) output projection, persistent grid (mode 0)
    split_w_kernel<<<dim3(HID / 32, HID / 32), 256>>>(Wout, B2, HID);
    gemm_bf16_kernel<<<296, 128, GSMEM_B>>>(A2, B2, out, HID, 0);
}

// round 15
// speedup vs baseline: 1.0139x; 1.0139x over previous
#include <cuda_runtime.h>
#include <cuda_bf16.h>
#include <math_constants.h>
#include <math.h>
#include <cstdint>

#define BATCH 2
#define SEQ   2048
#define HID   4096
#define NH    32
#define HDIM  128
#define QKVN  (3*HID)
#define MROWS (BATCH*SEQ)      // 4096
#define KSPLIT (3*HID)         // 12288 : 3-term split-concatenated K

// ---------------- scratch (device globals: allocation-guard safe) ----------
__device__ float         g_qkv[(size_t)MROWS * QKVN];     // only v third is used now
__device__ __nv_bfloat16 g_A2 [(size_t)MROWS * KSPLIT];   // [Ahi|Ahi|Alo]
__device__ __nv_bfloat16 g_B2 [(size_t)QKVN  * KSPLIT];   // [Bhi|Blo|Bhi] (N-major)
// flash operands: [bh][s][d] for q,k ; [bh][d][s] for v (transposed)
__device__ __nv_bfloat16 g_qhi[(size_t)BATCH * NH * SEQ * HDIM];
__device__ __nv_bfloat16 g_qlo[(size_t)BATCH * NH * SEQ * HDIM];
__device__ __nv_bfloat16 g_khi[(size_t)BATCH * NH * SEQ * HDIM];
__device__ __nv_bfloat16 g_klo[(size_t)BATCH * NH * SEQ * HDIM];
__device__ __nv_bfloat16 g_vhi[(size_t)BATCH * NH * SEQ * HDIM];
__device__ __nv_bfloat16 g_vlo[(size_t)BATCH * NH * SEQ * HDIM];
__device__ float2        g_rope[(size_t)MROWS * 32];      // (cos,sin) per (bs, j)

#define QSC (0.08838834764831845f * 1.4426950408889634f)  // 1/sqrt(128)*log2(e)

// ---------------- PTX helpers (sm_80-era, compute_103-safe) ----------------
__device__ __forceinline__ uint32_t smem_u32(const void* p) {
    uint32_t a;
    asm("{ .reg .u64 t; cvta.to.shared.u64 t, %1; cvt.u32.u64 %0, t; }" : "=r"(a) : "l"(p));
    return a;
}
__device__ __forceinline__ void cp16(uint32_t s, const void* g) {
    asm volatile("cp.async.cg.shared.global [%0], [%1], 16;" :: "r"(s), "l"(g) : "memory");
}
__device__ __forceinline__ void ldsm4(uint32_t* r, uint32_t addr) {
    asm volatile("ldmatrix.sync.aligned.m8n8.x4.shared.b16 {%0,%1,%2,%3}, [%4];"
                 : "=r"(r[0]), "=r"(r[1]), "=r"(r[2]), "=r"(r[3]) : "r"(addr));
}
__device__ __forceinline__ void mma_bf16(float* d, const uint32_t* a, uint32_t b0, uint32_t b1) {
    asm volatile("mma.sync.aligned.m16n8k16.row.col.f32.bf16.bf16.f32 "
                 "{%0,%1,%2,%3}, {%4,%5,%6,%7}, {%8,%9}, {%0,%1,%2,%3};"
                 : "+f"(d[0]), "+f"(d[1]), "+f"(d[2]), "+f"(d[3])
                 : "r"(a[0]), "r"(a[1]), "r"(a[2]), "r"(a[3]), "r"(b0), "r"(b1));
}
// pack: first arg -> low 16 bits (lower address), second -> high
__device__ __forceinline__ uint32_t pack_bf16(float lo, float hi) {
    uint32_t r;
    asm("cvt.rn.bf16x2.f32 %0, %1, %2;" : "=r"(r) : "f"(hi), "f"(lo));
    return r;
}
// fast 2^t on FMA pipe (no MUFU); t clamped at -120
__device__ __forceinline__ float exp2p(float t) {
    t = fmaxf(t, -120.f);
    float n = floorf(t);
    float f = t - n;
    float p = fmaf(f, 1.3333558e-4f, 1.3400431e-3f);
    p = fmaf(f, p, 9.6181291e-3f);
    p = fmaf(f, p, 5.5504109e-2f);
    p = fmaf(f, p, 2.4022651e-1f);
    p = fmaf(f, p, 6.9314718e-1f);
    p = fmaf(f, p, 1.0f);
    return p * __int_as_float(((int)n + 127) << 23);
}

struct alignas(8) bh4 { __nv_bfloat16 h[4]; };

// ============================================================================
// Split prepass 1: activations  src fp32 [M][4096] -> A2 bf16 [M][12288]
// ============================================================================
__global__ __launch_bounds__(256) void split_act_kernel(const float* __restrict__ src,
                                                        __nv_bfloat16* __restrict__ dst) {
    size_t i = (size_t)blockIdx.x * 256 + threadIdx.x;
    int row = (int)(i >> 10);
    int kc  = (int)(i & 1023);
    float4 v = ((const float4*)src)[i];
    bh4 hi, lo;
    hi.h[0] = __float2bfloat16(v.x); lo.h[0] = __float2bfloat16(v.x - __bfloat162float(hi.h[0]));
    hi.h[1] = __float2bfloat16(v.y); lo.h[1] = __float2bfloat16(v.y - __bfloat162float(hi.h[1]));
    hi.h[2] = __float2bfloat16(v.z); lo.h[2] = __float2bfloat16(v.z - __bfloat162float(hi.h[2]));
    hi.h[3] = __float2bfloat16(v.w); lo.h[3] = __float2bfloat16(v.w - __bfloat162float(hi.h[3]));
    __nv_bfloat16* d = dst + (size_t)row * KSPLIT + kc * 4;
    *(bh4*)(d)        = hi;
    *(bh4*)(d + 4096) = hi;
    *(bh4*)(d + 8192) = lo;
}

// ============================================================================
// Split prepass 2: weights  src fp32 [K=4096][N] -> B2 bf16 [N][12288]
// ============================================================================
__global__ __launch_bounds__(256) void split_w_kernel(const float* __restrict__ src,
                                                      __nv_bfloat16* __restrict__ dst,
                                                      int N) {
    __shared__ float t[32][33];
    int n0 = blockIdx.x * 32, k0 = blockIdx.y * 32;
    int tx = threadIdx.x & 31, ty = threadIdx.x >> 5;
#pragma unroll
    for (int i = 0; i < 4; i++)
        t[ty + i * 8][tx] = src[(size_t)(k0 + ty + i * 8) * N + n0 + tx];
    __syncthreads();
#pragma unroll
    for (int i = 0; i < 4; i++) {
        int n = n0 + ty + i * 8;
        int k = k0 + tx;
        float x = t[tx][ty + i * 8];
        __nv_bfloat16 hi = __float2bfloat16(x);
        __nv_bfloat16 lo = __float2bfloat16(x - __bfloat162float(hi));
        __nv_bfloat16* d = dst + (size_t)n * KSPLIT;
        d[k]        = hi;
        d[4096 + k] = lo;
        d[8192 + k] = hi;
    }
}

// ============================================================================
// RoPE table: g_rope[bs][j] = (cos, sin) of positions[bs] * theta^(-j/32)
// ============================================================================
__global__ __launch_bounds__(256) void rope_tab_kernel(const int* __restrict__ positions) {
    int i  = blockIdx.x * 256 + threadIdx.x;   // over MROWS*32
    int bs = i >> 5, j = i & 31;
    float pos = (float)positions[bs];
    float inv = powf(10000.0f, -(float)j * (1.0f / 32.0f));
    float sn, cs;
    sincosf(pos * inv, &sn, &cs);
    g_rope[i] = make_float2(cs, sn);
}

// ============================================================================
// bf16 tensor-core GEMM (R12 winner: R10 pipeline, non-persistent grid;
// mode 1 = fused RoPE + q/k split epilogue for the QKV projection)
// ============================================================================
#define GSTAGES   4
#define GROW_B    80
#define GTILE_B   (128 * GROW_B)
#define GSTAGE_B  (2 * GTILE_B)
#define GSMEM_B   (GSTAGES * GSTAGE_B)      // 81920

__global__ __launch_bounds__(128, 2) void gemm_bf16_kernel(const __nv_bfloat16* __restrict__ A,
                                                           const __nv_bfloat16* __restrict__ B,
                                                           float* __restrict__ C, int N,
                                                           int mode) {
    extern __shared__ char sm[];
    const int KT  = KSPLIT;
    const int NT  = KT / 32;
    const int tid  = threadIdx.x;
    const int lane = tid & 31;
    const int wid  = tid >> 5;
    const int wm   = wid & 1;
    const int wn   = wid >> 1;

    const int tiles_n = N >> 7;
    int bid  = blockIdx.x + blockIdx.y * gridDim.x;
    int band = bid / (8 * tiles_n);
    int rem  = bid % (8 * tiles_n);
    const int mt = band * 8 + (rem & 7);
    const int nt = rem >> 3;
    const int row0 = mt * 128, col0 = nt * 128;

    const __nv_bfloat16* Ab = A + (size_t)row0 * KT;
    const __nv_bfloat16* Bb = B + (size_t)col0 * KT;
    const uint32_t smb = smem_u32(sm);

    auto load_stage = [&](int s, int kt) {
        uint32_t sA = smb + s * GSTAGE_B;
        const __nv_bfloat16* ga = Ab + kt * 32;
        const __nv_bfloat16* gb = Bb + kt * 32;
#pragma unroll
        for (int i = 0; i < 4; i++) {
            int c   = tid + i * 128;
            int row = c >> 2;
            int kc  = c & 3;
            cp16(sA + row * GROW_B + kc * 16,           ga + (size_t)row * KT + kc * 8);
            cp16(sA + GTILE_B + row * GROW_B + kc * 16, gb + (size_t)row * KT + kc * 8);
        }
    };

    const int a_row = lane & 15;
    const int a_col = (lane >> 4) * 8;
    const int b_nl  = (lane & 7) + ((lane >> 4) & 1) * 8;
    const int b_kl  = ((lane >> 3) & 1) * 8;

    auto ldsm_half = [&](uint32_t af[4][4], uint32_t bf[4][4], int s, int ks) {
        const uint32_t aB = smb + s * GSTAGE_B;
        const uint32_t bB = aB + GTILE_B;
#pragma unroll
        for (int mf = 0; mf < 4; mf++)
            ldsm4(af[mf], aB + (uint32_t)((wm * 64 + mf * 16 + a_row) * GROW_B
                                          + (ks * 16 + a_col) * 2));
#pragma unroll
        for (int nf2 = 0; nf2 < 4; nf2++)
            ldsm4(bf[nf2], bB + (uint32_t)((wn * 64 + nf2 * 16 + b_nl) * GROW_B
                                           + (ks * 16 + b_kl) * 2));
    };

    float acc[4][8][4];
#pragma unroll
    for (int i = 0; i < 4; i++)
#pragma unroll
        for (int j = 0; j < 8; j++)
#pragma unroll
            for (int q = 0; q < 4; q++) acc[i][j][q] = 0.f;

    auto mma_half = [&](uint32_t af[4][4], uint32_t bf[4][4]) {
#pragma unroll
        for (int nf2 = 0; nf2 < 4; nf2++)
#pragma unroll
            for (int mf = 0; mf < 4; mf++) {
                mma_bf16(acc[mf][nf2 * 2],     af[mf], bf[nf2][0], bf[nf2][1]);
                mma_bf16(acc[mf][nf2 * 2 + 1], af[mf], bf[nf2][2], bf[nf2][3]);
            }
    };

    load_stage(0, 0); asm volatile("cp.async.commit_group;" ::: "memory");
    load_stage(1, 1); asm volatile("cp.async.commit_group;" ::: "memory");
    load_stage(2, 2); asm volatile("cp.async.commit_group;" ::: "memory");

    uint32_t af0[4][4], bf0[4][4], af1[4][4], bf1[4][4];

    asm volatile("cp.async.wait_group 2;" ::: "memory");
    __syncthreads();
    ldsm_half(af0, bf0, 0, 0);

    for (int kt = 0; kt < NT; kt++) {
        const int s = kt & 3;

        ldsm_half(af1, bf1, s, 1);
        mma_half(af0, bf0);

        if (kt + 3 < NT) load_stage((kt + 3) & 3, kt + 3);
        asm volatile("cp.async.commit_group;" ::: "memory");

        if (kt + 1 < NT) {
            asm volatile("cp.async.wait_group 2;" ::: "memory");
            __syncthreads();
            ldsm_half(af0, bf0, (kt + 1) & 3, 0);
        }
        mma_half(af1, bf1);
    }

    // ------------------------------ epilogue ------------------------------
    const int sec = col0 >> 12;   // mode 1: 0=q, 1=k, 2=v
    if (mode == 0 || sec == 2) {
#pragma unroll
        for (int mf = 0; mf < 4; mf++)
#pragma unroll
            for (int nf = 0; nf < 8; nf++) {
                int r  = row0 + wm * 64 + mf * 16 + (lane >> 2);
                int cc = col0 + wn * 64 + nf * 8 + (lane & 3) * 2;
                *(float2*)&C[(size_t)r * N + cc]       = make_float2(acc[mf][nf][0], acc[mf][nf][1]);
                *(float2*)&C[(size_t)(r + 8) * N + cc] = make_float2(acc[mf][nf][2], acc[mf][nf][3]);
            }
    } else {
        const int h   = (col0 & 4095) >> 7;
        const bool rot = (wn == 0);
        __nv_bfloat16* dhi = (sec == 0) ? g_qhi : g_khi;
        __nv_bfloat16* dlo = (sec == 0) ? g_qlo : g_klo;
        const float scl = (sec == 0) ? QSC : 1.0f;
#pragma unroll
        for (int mf = 0; mf < 4; mf++)
#pragma unroll
            for (int rr = 0; rr < 2; rr++) {
                int r  = row0 + wm * 64 + mf * 16 + (lane >> 2) + rr * 8;
                int bb = r >> 11, ss = r & 2047;
                float vals[8][2];
#pragma unroll
                for (int nf = 0; nf < 8; nf++) {
                    vals[nf][0] = acc[mf][nf][rr * 2 + 0];
                    vals[nf][1] = acc[mf][nf][rr * 2 + 1];
                }
                if (rot) {
#pragma unroll
                    for (int nf = 0; nf < 4; nf++)
#pragma unroll
                        for (int q = 0; q < 2; q++) {
                            int j = nf * 8 + (lane & 3) * 2 + q;
                            float2 t = g_rope[(size_t)r * 32 + j];
                            float x1 = vals[nf][q], x2 = vals[nf + 4][q];
                            vals[nf][q]     = x1 * t.x - x2 * t.y;
                            vals[nf + 4][q] = x2 * t.x + x1 * t.y;
                        }
                }
                size_t base = ((size_t)(bb * NH + h) * SEQ + ss) * HDIM
                              + wn * 64 + (lane & 3) * 2;
#pragma unroll
                for (int nf = 0; nf < 8; nf++) {
                    float x0 = vals[nf][0] * scl;
                    float x1 = vals[nf][1] * scl;
                    float h0 = __bfloat162float(__float2bfloat16(x0));
                    float h1 = __bfloat162float(__float2bfloat16(x1));
                    *(uint32_t*)&dhi[base + nf * 8] = pack_bf16(x0, x1);
                    *(uint32_t*)&dlo[base + nf * 8] = pack_bf16(x0 - h0, x1 - h1);
                }
            }
    }
}

// ============================================================================
// Flash prepass B: split v to bf16 hi/lo TRANSPOSED, layout [bh][d][s]
// ============================================================================
__global__ __launch_bounds__(256) void split_v_kernel() {
    __shared__ float t[32][33];
    int s0 = blockIdx.x * 32;
    int d0 = blockIdx.y * 32;
    int bh = blockIdx.z;
    int b  = bh >> 5, h = bh & 31;
    int tx = threadIdx.x & 31, ty = threadIdx.x >> 5;
#pragma unroll
    for (int i = 0; i < 4; i++)
        t[ty + i * 8][tx] = g_qkv[((size_t)(b * SEQ + s0 + ty + i * 8)) * QKVN
                                  + 2 * HID + h * HDIM + d0 + tx];
    __syncthreads();
#pragma unroll
    for (int i = 0; i < 4; i++) {
        int d = d0 + ty + i * 8;
        float x = t[tx][ty + i * 8];
        __nv_bfloat16 hi = __float2bfloat16(x);
        __nv_bfloat16 lo = __float2bfloat16(x - __bfloat162float(hi));
        size_t dst = ((size_t)bh * HDIM + d) * SEQ + s0 + tx;
        g_vhi[dst] = hi;
        g_vlo[dst] = lo;
    }
}

// ============================================================================
// Tensor-core flash attention (bf16 hi/lo 3-term), causal.
// Deferred l-reduction (alpha uniform within quad); Q fragments from smem.
// Epilogue writes bf16 3-term A-operand [Ahi|Ahi|Alo] for the out-projection.
// ============================================================================
#define FQ   128
#define FK   64
#define QROWB 272
#define VROWB 144
#define OQH  0
#define OQL  34816
#define OST  69632
#define FKL  17408
#define FVH  34816
#define FVL  53248
#define FSTAGE 71680
#define FSMEM (OST + 2 * FSTAGE)   // 212992

__global__ __launch_bounds__(256, 1) void flash_tc_kernel() {
    extern __shared__ char sm[];
    const uint32_t smb = smem_u32(sm);
    const int tid  = threadIdx.x;
    const int lane = tid & 31;
    const int w    = tid >> 5;
    const int qt   = gridDim.x - 1 - blockIdx.x;
    const int bh   = blockIdx.y;
    const int ntiles = 2 * qt + 2;

    {
        size_t qoff = ((size_t)bh * SEQ + (size_t)qt * FQ) * HDIM;
#pragma unroll
        for (int i = tid; i < 2048; i += 256) {
            int r = i >> 4, c = i & 15;
            cp16(smb + OQH + r * QROWB + c * 16, g_qhi + qoff + (size_t)r * HDIM + c * 8);
            cp16(smb + OQL + r * QROWB + c * 16, g_qlo + qoff + (size_t)r * HDIM + c * 8);
        }
    }

    auto load_kv = [&](int st, int kt) {
        uint32_t sb = smb + OST + st * FSTAGE;
        size_t koff = ((size_t)bh * SEQ + (size_t)kt * FK) * HDIM;
#pragma unroll
        for (int i = tid; i < 1024; i += 256) {
            int r = i >> 4, c = i & 15;
            cp16(sb + r * QROWB + c * 16,       g_khi + koff + (size_t)r * HDIM + c * 8);
            cp16(sb + FKL + r * QROWB + c * 16, g_klo + koff + (size_t)r * HDIM + c * 8);
        }
        size_t voff = (size_t)bh * HDIM * SEQ + (size_t)kt * FK;
#pragma unroll
        for (int i = tid; i < 1024; i += 256) {
            int d = i >> 3, c = i & 7;
            cp16(sb + FVH + d * VROWB + c * 16, g_vhi + voff + (size_t)d * SEQ + c * 8);
            cp16(sb + FVL + d * VROWB + c * 16, g_vlo + voff + (size_t)d * SEQ + c * 8);
        }
    };

    load_kv(0, 0);
    asm volatile("cp.async.commit_group;" ::: "memory");

    float o[16][4];
#pragma unroll
    for (int i = 0; i < 16; i++)
#pragma unroll
        for (int j = 0; j < 4; j++) o[i][j] = 0.f;
    float m0 = -CUDART_INF_F, m1 = -CUDART_INF_F, l0 = 0.f, l1 = 0.f;

    const int a_row = lane & 15;
    const int a_col = (lane >> 4) * 8;
    const int b_nl  = (lane & 7) + ((lane >> 4) & 1) * 8;
    const int b_kl  = ((lane >> 3) & 1) * 8;
    const int qrow0 = qt * FQ + w * 16 + (lane >> 2);

    for (int kt = 0; kt < ntiles; kt++) {
        if (kt + 1 < ntiles) load_kv((kt + 1) & 1, kt + 1);
        asm volatile("cp.async.commit_group;" ::: "memory");
        asm volatile("cp.async.wait_group 1;" ::: "memory");
        __syncthreads();

        const uint32_t kb = smb + OST + (kt & 1) * FSTAGE;
        const uint32_t vb = kb + FVH;

        float s[8][4];
#pragma unroll
        for (int i = 0; i < 8; i++)
#pragma unroll
            for (int j = 0; j < 4; j++) s[i][j] = 0.f;

#pragma unroll
        for (int ks = 0; ks < 8; ks++) {
            uint32_t qh[4], ql[4];
            uint32_t qaddr = smb + OQH + (uint32_t)((w * 16 + a_row) * QROWB + (ks * 16 + a_col) * 2);
            ldsm4(qh, qaddr);
            ldsm4(ql, qaddr + (OQL - OQH));
#pragma unroll
            for (int nt2 = 0; nt2 < 4; nt2++) {
                uint32_t kh[4], kl[4];
                uint32_t kaddr = kb + (uint32_t)((nt2 * 16 + b_nl) * QROWB + (ks * 16 + b_kl) * 2);
                ldsm4(kh, kaddr);
                ldsm4(kl, kaddr + FKL);
                mma_bf16(s[nt2 * 2],     qh, kh[0], kh[1]);
                mma_bf16(s[nt2 * 2 + 1], qh, kh[2], kh[3]);
                mma_bf16(s[nt2 * 2],     qh, kl[0], kl[1]);
                mma_bf16(s[nt2 * 2 + 1], qh, kl[2], kl[3]);
                mma_bf16(s[nt2 * 2],     ql, kh[0], kh[1]);
                mma_bf16(s[nt2 * 2 + 1], ql, kh[2], kh[3]);
            }
        }

        if (kt * FK + FK - 1 > qt * FQ + w * 16) {
#pragma unroll
            for (int nt = 0; nt < 8; nt++) {
                int key = kt * FK + nt * 8 + (lane & 3) * 2;
                if (key     > qrow0)     s[nt][0] = -CUDART_INF_F;
                if (key + 1 > qrow0)     s[nt][1] = -CUDART_INF_F;
                if (key     > qrow0 + 8) s[nt][2] = -CUDART_INF_F;
                if (key + 1 > qrow0 + 8) s[nt][3] = -CUDART_INF_F;
            }
        }

        float mx0 = -CUDART_INF_F, mx1 = -CUDART_INF_F;
#pragma unroll
        for (int nt = 0; nt < 8; nt++) {
            mx0 = fmaxf(mx0, fmaxf(s[nt][0], s[nt][1]));
            mx1 = fmaxf(mx1, fmaxf(s[nt][2], s[nt][3]));
        }
        mx0 = fmaxf(mx0, __shfl_xor_sync(0xffffffffu, mx0, 1));
        mx0 = fmaxf(mx0, __shfl_xor_sync(0xffffffffu, mx0, 2));
        mx1 = fmaxf(mx1, __shfl_xor_sync(0xffffffffu, mx1, 1));
        mx1 = fmaxf(mx1, __shfl_xor_sync(0xffffffffu, mx1, 2));
        float mn0 = fmaxf(m0, mx0), mn1 = fmaxf(m1, mx1);
        float al0 = exp2p(m0 - mn0), al1 = exp2p(m1 - mn1);
        m0 = mn0; m1 = mn1;

        float sum0 = 0.f, sum1 = 0.f;
#pragma unroll
        for (int nt = 0; nt < 8; nt++) {
            s[nt][0] = exp2p(s[nt][0] - mn0); sum0 += s[nt][0];
            s[nt][1] = exp2p(s[nt][1] - mn0); sum0 += s[nt][1];
            s[nt][2] = exp2p(s[nt][2] - mn1); sum1 += s[nt][2];
            s[nt][3] = exp2p(s[nt][3] - mn1); sum1 += s[nt][3];
        }
        // deferred l-reduction: per-thread quarter-row partials (reduced once
        // in the epilogue; alpha is uniform within each lane quad)
        l0 = l0 * al0 + sum0;
        l1 = l1 * al1 + sum1;

#pragma unroll
        for (int nt = 0; nt < 16; nt++) {
            o[nt][0] *= al0; o[nt][1] *= al0;
            o[nt][2] *= al1; o[nt][3] *= al1;
        }

#pragma unroll
        for (int g = 0; g < 4; g++) {
            float h00 = __bfloat162float(__float2bfloat16(s[2*g][0]));
            float h01 = __bfloat162float(__float2bfloat16(s[2*g][1]));
            float h02 = __bfloat162float(__float2bfloat16(s[2*g][2]));
            float h03 = __bfloat162float(__float2bfloat16(s[2*g][3]));
            float h10 = __bfloat162float(__float2bfloat16(s[2*g+1][0]));
            float h11 = __bfloat162float(__float2bfloat16(s[2*g+1][1]));
            float h12 = __bfloat162float(__float2bfloat16(s[2*g+1][2]));
            float h13 = __bfloat162float(__float2bfloat16(s[2*g+1][3]));
            uint32_t phi[4], plo[4];
            phi[0] = pack_bf16(h00, h01);
            phi[1] = pack_bf16(h02, h03);
            phi[2] = pack_bf16(h10, h11);
            phi[3] = pack_bf16(h12, h13);
            plo[0] = pack_bf16(s[2*g][0] - h00,   s[2*g][1] - h01);
            plo[1] = pack_bf16(s[2*g][2] - h02,   s[2*g][3] - h03);
            plo[2] = pack_bf16(s[2*g+1][0] - h10, s[2*g+1][1] - h11);
            plo[3] = pack_bf16(s[2*g+1][2] - h12, s[2*g+1][3] - h13);

#pragma unroll
            for (int dt2 = 0; dt2 < 8; dt2++) {
                uint32_t vh[4], vl[4];
                uint32_t vaddr = vb + (uint32_t)((dt2 * 16 + b_nl) * VROWB + (g * 16 + b_kl) * 2);
                ldsm4(vh, vaddr);
                ldsm4(vl, vaddr + (FVL - FVH));
                mma_bf16(o[dt2 * 2],     phi, vh[0], vh[1]);
                mma_bf16(o[dt2 * 2 + 1], phi, vh[2], vh[3]);
                mma_bf16(o[dt2 * 2],     phi, vl[0], vl[1]);
                mma_bf16(o[dt2 * 2 + 1], phi, vl[2], vl[3]);
                mma_bf16(o[dt2 * 2],     plo, vh[0], vh[1]);
                mma_bf16(o[dt2 * 2 + 1], plo, vh[2], vh[3]);
            }
        }
        __syncthreads();
    }

    // ---- deferred cross-thread l reduction ----
    l0 += __shfl_xor_sync(0xffffffffu, l0, 1);
    l0 += __shfl_xor_sync(0xffffffffu, l0, 2);
    l1 += __shfl_xor_sync(0xffffffffu, l1, 1);
    l1 += __shfl_xor_sync(0xffffffffu, l1, 2);

    // ---- epilogue: write bf16 [Ahi|Ahi|Alo] A-operand rows into g_A2 ----
    const float invl0 = 1.0f / l0;
    const float invl1 = 1.0f / l1;
    const int b = bh >> 5, h = bh & 31;
    const size_t r0 = (size_t)(b * SEQ + qt * FQ + w * 16 + (lane >> 2));
#pragma unroll
    for (int nt = 0; nt < 16; nt++) {
        size_t cbase = (size_t)h * HDIM + nt * 8 + (lane & 3) * 2;
        float x0 = o[nt][0] * invl0, x1 = o[nt][1] * invl0;
        float x2 = o[nt][2] * invl1, x3 = o[nt][3] * invl1;

        float h0 = __bfloat162float(__float2bfloat16(x0));
        float h1 = __bfloat162float(__float2bfloat16(x1));
        float h2 = __bfloat162float(__float2bfloat16(x2));
        float h3 = __bfloat162float(__float2bfloat16(x3));
        uint32_t hi01 = pack_bf16(x0, x1);
        uint32_t lo01 = pack_bf16(x0 - h0, x1 - h1);
        uint32_t hi23 = pack_bf16(x2, x3);
        uint32_t lo23 = pack_bf16(x2 - h2, x3 - h3);

        __nv_bfloat16* a0 = &g_A2[r0 * KSPLIT + cbase];
        __nv_bfloat16* a1 = &g_A2[(r0 + 8) * KSPLIT + cbase];
        *(uint32_t*)(a0)        = hi01;
        *(uint32_t*)(a0 + 4096) = hi01;
        *(uint32_t*)(a0 + 8192) = lo01;
        *(uint32_t*)(a1)        = hi23;
        *(uint32_t*)(a1 + 4096) = hi23;
        *(uint32_t*)(a1 + 8192) = lo23;
    }
}

// ============================================================================
extern "C" void kernel_launch(void* const* d_in, const int* in_sizes, int n_in,
                              void* d_out, int out_size) {
    const float* hidden    = (const float*)d_in[0];
    const int*   positions = (const int*)d_in[1];
    const float* Wqkv      = (const float*)d_in[2];
    const float* Wout      = (const float*)d_in[3];
    float*       out       = (float*)d_out;

    float*         qkv; cudaGetSymbolAddress((void**)&qkv, g_qkv);
    __nv_bfloat16* A2;  cudaGetSymbolAddress((void**)&A2,  g_A2);
    __nv_bfloat16* B2;  cudaGetSymbolAddress((void**)&B2,  g_B2);

    static bool attr_done = false;
    if (!attr_done) {
        cudaFuncSetAttribute(gemm_bf16_kernel, cudaFuncAttributeMaxDynamicSharedMemorySize, GSMEM_B);
        cudaFuncSetAttribute(flash_tc_kernel, cudaFuncAttributeMaxDynamicSharedMemorySize, FSMEM);
        attr_done = true;
    }

    // 1) split hidden -> A2, Wqkv -> B2 (bf16 3-term) ; rope table
    split_act_kernel<<<(MROWS * (HID / 4)) / 256, 256>>>(hidden, A2);
    split_w_kernel<<<dim3(QKVN / 32, HID / 32), 256>>>(Wqkv, B2, QKVN);
    rope_tab_kernel<<<(MROWS * 32) / 256, 256>>>(positions);

    // 2) QKV projection with FUSED rope + q/k split in the epilogue (mode 1)
    gemm_bf16_kernel<<<dim3(QKVN / 128, MROWS / 128), 128, GSMEM_B>>>(A2, B2, qkv, QKVN, 1);

    // 3) split v (transposed)
    split_v_kernel<<<dim3(SEQ / 32, HDIM / 32, BATCH * NH), 256>>>();

    // 4) tensor-core causal flash attention (writes A2 for out-proj)
    flash_tc_kernel<<<dim3(SEQ / FQ, BATCH * NH), 256, FSMEM>>>();

    // 5) output projection (mode 0)
    split_w_kernel<<<dim3(HID / 32, HID / 32), 256>>>(Wout, B2, HID);
    gemm_bf16_kernel<<<dim3(HID / 128, MROWS / 128), 128, GSMEM_B>>>(A2, B2, out, HID, 0);
}

// round 16
// speedup vs baseline: 1.0362x; 1.0220x over previous
#include <cuda_runtime.h>
#include <cuda_bf16.h>
#include <math_constants.h>
#include <math.h>
#include <cstdint>

#define BATCH 2
#define SEQ   2048
#define HID   4096
#define NH    32
#define HDIM  128
#define QKVN  (3*HID)
#define MROWS (BATCH*SEQ)      // 4096
#define KSPLIT (3*HID)         // 12288 : 3-term split-concatenated K

// ---------------- scratch (device globals: allocation-guard safe) ----------
__device__ float         g_qkv[(size_t)MROWS * QKVN];     // only v third is used now
__device__ __nv_bfloat16 g_A2 [(size_t)MROWS * KSPLIT];   // [Ahi|Ahi|Alo]
__device__ __nv_bfloat16 g_B2 [(size_t)QKVN  * KSPLIT];   // [Bhi|Blo|Bhi] (N-major)
// flash operands: [bh][s][d] for q,k ; [bh][d][s] for v (transposed)
__device__ __nv_bfloat16 g_qhi[(size_t)BATCH * NH * SEQ * HDIM];
__device__ __nv_bfloat16 g_qlo[(size_t)BATCH * NH * SEQ * HDIM];
__device__ __nv_bfloat16 g_khi[(size_t)BATCH * NH * SEQ * HDIM];
__device__ __nv_bfloat16 g_klo[(size_t)BATCH * NH * SEQ * HDIM];
__device__ __nv_bfloat16 g_vhi[(size_t)BATCH * NH * SEQ * HDIM];
__device__ __nv_bfloat16 g_vlo[(size_t)BATCH * NH * SEQ * HDIM];
__device__ float2        g_rope[(size_t)MROWS * 32];      // (cos,sin) per (bs, j)

#define QSC (0.08838834764831845f * 1.4426950408889634f)  // 1/sqrt(128)*log2(e)

// ---------------- PTX helpers (sm_80-era, compute_103-safe) ----------------
__device__ __forceinline__ uint32_t smem_u32(const void* p) {
    uint32_t a;
    asm("{ .reg .u64 t; cvta.to.shared.u64 t, %1; cvt.u32.u64 %0, t; }" : "=r"(a) : "l"(p));
    return a;
}
__device__ __forceinline__ void cp16(uint32_t s, const void* g) {
    asm volatile("cp.async.cg.shared.global [%0], [%1], 16;" :: "r"(s), "l"(g) : "memory");
}
__device__ __forceinline__ void ldsm4(uint32_t* r, uint32_t addr) {
    asm volatile("ldmatrix.sync.aligned.m8n8.x4.shared.b16 {%0,%1,%2,%3}, [%4];"
                 : "=r"(r[0]), "=r"(r[1]), "=r"(r[2]), "=r"(r[3]) : "r"(addr));
}
__device__ __forceinline__ void mma_bf16(float* d, const uint32_t* a, uint32_t b0, uint32_t b1) {
    asm volatile("mma.sync.aligned.m16n8k16.row.col.f32.bf16.bf16.f32 "
                 "{%0,%1,%2,%3}, {%4,%5,%6,%7}, {%8,%9}, {%0,%1,%2,%3};"
                 : "+f"(d[0]), "+f"(d[1]), "+f"(d[2]), "+f"(d[3])
                 : "r"(a[0]), "r"(a[1]), "r"(a[2]), "r"(a[3]), "r"(b0), "r"(b1));
}
// pack: first arg -> low 16 bits (lower address), second -> high
__device__ __forceinline__ uint32_t pack_bf16(float lo, float hi) {
    uint32_t r;
    asm("cvt.rn.bf16x2.f32 %0, %1, %2;" : "=r"(r) : "f"(hi), "f"(lo));
    return r;
}
// fast 2^t on FMA pipe (no MUFU); t clamped at -120
__device__ __forceinline__ float exp2p(float t) {
    t = fmaxf(t, -120.f);
    float n = floorf(t);
    float f = t - n;
    float p = fmaf(f, 1.3333558e-4f, 1.3400431e-3f);
    p = fmaf(f, p, 9.6181291e-3f);
    p = fmaf(f, p, 5.5504109e-2f);
    p = fmaf(f, p, 2.4022651e-1f);
    p = fmaf(f, p, 6.9314718e-1f);
    p = fmaf(f, p, 1.0f);
    return p * __int_as_float(((int)n + 127) << 23);
}

struct alignas(8) bh4 { __nv_bfloat16 h[4]; };

// ============================================================================
// Split prepass 1: activations  src fp32 [M][4096] -> A2 bf16 [M][12288]
// ============================================================================
__global__ __launch_bounds__(256) void split_act_kernel(const float* __restrict__ src,
                                                        __nv_bfloat16* __restrict__ dst) {
    size_t i = (size_t)blockIdx.x * 256 + threadIdx.x;
    int row = (int)(i >> 10);
    int kc  = (int)(i & 1023);
    float4 v = ((const float4*)src)[i];
    bh4 hi, lo;
    hi.h[0] = __float2bfloat16(v.x); lo.h[0] = __float2bfloat16(v.x - __bfloat162float(hi.h[0]));
    hi.h[1] = __float2bfloat16(v.y); lo.h[1] = __float2bfloat16(v.y - __bfloat162float(hi.h[1]));
    hi.h[2] = __float2bfloat16(v.z); lo.h[2] = __float2bfloat16(v.z - __bfloat162float(hi.h[2]));
    hi.h[3] = __float2bfloat16(v.w); lo.h[3] = __float2bfloat16(v.w - __bfloat162float(hi.h[3]));
    __nv_bfloat16* d = dst + (size_t)row * KSPLIT + kc * 4;
    *(bh4*)(d)        = hi;
    *(bh4*)(d + 4096) = hi;
    *(bh4*)(d + 8192) = lo;
}

// ============================================================================
// Split prepass 2: weights  src fp32 [K=4096][N] -> B2 bf16 [N][12288]
// ============================================================================
__global__ __launch_bounds__(256) void split_w_kernel(const float* __restrict__ src,
                                                      __nv_bfloat16* __restrict__ dst,
                                                      int N) {
    __shared__ float t[32][33];
    int n0 = blockIdx.x * 32, k0 = blockIdx.y * 32;
    int tx = threadIdx.x & 31, ty = threadIdx.x >> 5;
#pragma unroll
    for (int i = 0; i < 4; i++)
        t[ty + i * 8][tx] = src[(size_t)(k0 + ty + i * 8) * N + n0 + tx];
    __syncthreads();
#pragma unroll
    for (int i = 0; i < 4; i++) {
        int n = n0 + ty + i * 8;
        int k = k0 + tx;
        float x = t[tx][ty + i * 8];
        __nv_bfloat16 hi = __float2bfloat16(x);
        __nv_bfloat16 lo = __float2bfloat16(x - __bfloat162float(hi));
        __nv_bfloat16* d = dst + (size_t)n * KSPLIT;
        d[k]        = hi;
        d[4096 + k] = lo;
        d[8192 + k] = hi;
    }
}

// ============================================================================
// RoPE table: g_rope[bs][j] = (cos, sin) of positions[bs] * theta^(-j/32)
// ============================================================================
__global__ __launch_bounds__(256) void rope_tab_kernel(const int* __restrict__ positions) {
    int i  = blockIdx.x * 256 + threadIdx.x;   // over MROWS*32
    int bs = i >> 5, j = i & 31;
    float pos = (float)positions[bs];
    float inv = powf(10000.0f, -(float)j * (1.0f / 32.0f));
    float sn, cs;
    sincosf(pos * inv, &sn, &cs);
    g_rope[i] = make_float2(cs, sn);
}

// ============================================================================
// bf16 tensor-core GEMM (R12 winner: R10 pipeline, non-persistent grid;
// mode 1 = fused RoPE + q/k split epilogue for the QKV projection)
// ============================================================================
#define GSTAGES   4
#define GROW_B    80
#define GTILE_B   (128 * GROW_B)
#define GSTAGE_B  (2 * GTILE_B)
#define GSMEM_B   (GSTAGES * GSTAGE_B)      // 81920

__global__ __launch_bounds__(128, 2) void gemm_bf16_kernel(const __nv_bfloat16* __restrict__ A,
                                                           const __nv_bfloat16* __restrict__ B,
                                                           float* __restrict__ C, int N,
                                                           int mode) {
    extern __shared__ char sm[];
    const int KT  = KSPLIT;
    const int NT  = KT / 32;
    const int tid  = threadIdx.x;
    const int lane = tid & 31;
    const int wid  = tid >> 5;
    const int wm   = wid & 1;
    const int wn   = wid >> 1;

    const int tiles_n = N >> 7;
    int bid  = blockIdx.x + blockIdx.y * gridDim.x;
    int band = bid / (8 * tiles_n);
    int rem  = bid % (8 * tiles_n);
    const int mt = band * 8 + (rem & 7);
    const int nt = rem >> 3;
    const int row0 = mt * 128, col0 = nt * 128;

    const __nv_bfloat16* Ab = A + (size_t)row0 * KT;
    const __nv_bfloat16* Bb = B + (size_t)col0 * KT;
    const uint32_t smb = smem_u32(sm);

    auto load_stage = [&](int s, int kt) {
        uint32_t sA = smb + s * GSTAGE_B;
        const __nv_bfloat16* ga = Ab + kt * 32;
        const __nv_bfloat16* gb = Bb + kt * 32;
#pragma unroll
        for (int i = 0; i < 4; i++) {
            int c   = tid + i * 128;
            int row = c >> 2;
            int kc  = c & 3;
            cp16(sA + row * GROW_B + kc * 16,           ga + (size_t)row * KT + kc * 8);
            cp16(sA + GTILE_B + row * GROW_B + kc * 16, gb + (size_t)row * KT + kc * 8);
        }
    };

    const int a_row = lane & 15;
    const int a_col = (lane >> 4) * 8;
    const int b_nl  = (lane & 7) + ((lane >> 4) & 1) * 8;
    const int b_kl  = ((lane >> 3) & 1) * 8;

    auto ldsm_half = [&](uint32_t af[4][4], uint32_t bf[4][4], int s, int ks) {
        const uint32_t aB = smb + s * GSTAGE_B;
        const uint32_t bB = aB + GTILE_B;
#pragma unroll
        for (int mf = 0; mf < 4; mf++)
            ldsm4(af[mf], aB + (uint32_t)((wm * 64 + mf * 16 + a_row) * GROW_B
                                          + (ks * 16 + a_col) * 2));
#pragma unroll
        for (int nf2 = 0; nf2 < 4; nf2++)
            ldsm4(bf[nf2], bB + (uint32_t)((wn * 64 + nf2 * 16 + b_nl) * GROW_B
                                           + (ks * 16 + b_kl) * 2));
    };

    float acc[4][8][4];
#pragma unroll
    for (int i = 0; i < 4; i++)
#pragma unroll
        for (int j = 0; j < 8; j++)
#pragma unroll
            for (int q = 0; q < 4; q++) acc[i][j][q] = 0.f;

    auto mma_half = [&](uint32_t af[4][4], uint32_t bf[4][4]) {
#pragma unroll
        for (int nf2 = 0; nf2 < 4; nf2++)
#pragma unroll
            for (int mf = 0; mf < 4; mf++) {
                mma_bf16(acc[mf][nf2 * 2],     af[mf], bf[nf2][0], bf[nf2][1]);
                mma_bf16(acc[mf][nf2 * 2 + 1], af[mf], bf[nf2][2], bf[nf2][3]);
            }
    };

    load_stage(0, 0); asm volatile("cp.async.commit_group;" ::: "memory");
    load_stage(1, 1); asm volatile("cp.async.commit_group;" ::: "memory");
    load_stage(2, 2); asm volatile("cp.async.commit_group;" ::: "memory");

    uint32_t af0[4][4], bf0[4][4], af1[4][4], bf1[4][4];

    asm volatile("cp.async.wait_group 2;" ::: "memory");
    __syncthreads();
    ldsm_half(af0, bf0, 0, 0);

    for (int kt = 0; kt < NT; kt++) {
        const int s = kt & 3;

        ldsm_half(af1, bf1, s, 1);
        mma_half(af0, bf0);

        if (kt + 3 < NT) load_stage((kt + 3) & 3, kt + 3);
        asm volatile("cp.async.commit_group;" ::: "memory");

        if (kt + 1 < NT) {
            asm volatile("cp.async.wait_group 2;" ::: "memory");
            __syncthreads();
            ldsm_half(af0, bf0, (kt + 1) & 3, 0);
        }
        mma_half(af1, bf1);
    }

    // ------------------------------ epilogue ------------------------------
    const int sec = col0 >> 12;   // mode 1: 0=q, 1=k, 2=v
    if (mode == 0 || sec == 2) {
#pragma unroll
        for (int mf = 0; mf < 4; mf++)
#pragma unroll
            for (int nf = 0; nf < 8; nf++) {
                int r  = row0 + wm * 64 + mf * 16 + (lane >> 2);
                int cc = col0 + wn * 64 + nf * 8 + (lane & 3) * 2;
                *(float2*)&C[(size_t)r * N + cc]       = make_float2(acc[mf][nf][0], acc[mf][nf][1]);
                *(float2*)&C[(size_t)(r + 8) * N + cc] = make_float2(acc[mf][nf][2], acc[mf][nf][3]);
            }
    } else {
        const int h   = (col0 & 4095) >> 7;
        const bool rot = (wn == 0);
        __nv_bfloat16* dhi = (sec == 0) ? g_qhi : g_khi;
        __nv_bfloat16* dlo = (sec == 0) ? g_qlo : g_klo;
        const float scl = (sec == 0) ? QSC : 1.0f;
#pragma unroll
        for (int mf = 0; mf < 4; mf++)
#pragma unroll
            for (int rr = 0; rr < 2; rr++) {
                int r  = row0 + wm * 64 + mf * 16 + (lane >> 2) + rr * 8;
                int bb = r >> 11, ss = r & 2047;
                float vals[8][2];
#pragma unroll
                for (int nf = 0; nf < 8; nf++) {
                    vals[nf][0] = acc[mf][nf][rr * 2 + 0];
                    vals[nf][1] = acc[mf][nf][rr * 2 + 1];
                }
                if (rot) {
#pragma unroll
                    for (int nf = 0; nf < 4; nf++)
#pragma unroll
                        for (int q = 0; q < 2; q++) {
                            int j = nf * 8 + (lane & 3) * 2 + q;
                            float2 t = g_rope[(size_t)r * 32 + j];
                            float x1 = vals[nf][q], x2 = vals[nf + 4][q];
                            vals[nf][q]     = x1 * t.x - x2 * t.y;
                            vals[nf + 4][q] = x2 * t.x + x1 * t.y;
                        }
                }
                size_t base = ((size_t)(bb * NH + h) * SEQ + ss) * HDIM
                              + wn * 64 + (lane & 3) * 2;
#pragma unroll
                for (int nf = 0; nf < 8; nf++) {
                    float x0 = vals[nf][0] * scl;
                    float x1 = vals[nf][1] * scl;
                    float h0 = __bfloat162float(__float2bfloat16(x0));
                    float h1 = __bfloat162float(__float2bfloat16(x1));
                    *(uint32_t*)&dhi[base + nf * 8] = pack_bf16(x0, x1);
                    *(uint32_t*)&dlo[base + nf * 8] = pack_bf16(x0 - h0, x1 - h1);
                }
            }
    }
}

// ============================================================================
// Flash prepass B: split v to bf16 hi/lo TRANSPOSED, layout [bh][d][s]
// ============================================================================
__global__ __launch_bounds__(256) void split_v_kernel() {
    __shared__ float t[32][33];
    int s0 = blockIdx.x * 32;
    int d0 = blockIdx.y * 32;
    int bh = blockIdx.z;
    int b  = bh >> 5, h = bh & 31;
    int tx = threadIdx.x & 31, ty = threadIdx.x >> 5;
#pragma unroll
    for (int i = 0; i < 4; i++)
        t[ty + i * 8][tx] = g_qkv[((size_t)(b * SEQ + s0 + ty + i * 8)) * QKVN
                                  + 2 * HID + h * HDIM + d0 + tx];
    __syncthreads();
#pragma unroll
    for (int i = 0; i < 4; i++) {
        int d = d0 + ty + i * 8;
        float x = t[tx][ty + i * 8];
        __nv_bfloat16 hi = __float2bfloat16(x);
        __nv_bfloat16 lo = __float2bfloat16(x - __bfloat162float(hi));
        size_t dst = ((size_t)bh * HDIM + d) * SEQ + s0 + tx;
        g_vhi[dst] = hi;
        g_vlo[dst] = lo;
    }
}

// ============================================================================
// Tensor-core flash attention (bf16 hi/lo 3-term), causal.
// Grid: x = bh (fast-varying), y = qt index — LPT dispatch: all 32-step CTAs
// (qt=15) launch first, 2-step CTAs last. Deferred l-reduction.
// Epilogue writes bf16 3-term A-operand [Ahi|Ahi|Alo] for the out-projection.
// ============================================================================
#define FQ   128
#define FK   64
#define QROWB 272
#define VROWB 144
#define OQH  0
#define OQL  34816
#define OST  69632
#define FKL  17408
#define FVH  34816
#define FVL  53248
#define FSTAGE 71680
#define FSMEM (OST + 2 * FSTAGE)   // 212992

__global__ __launch_bounds__(256, 1) void flash_tc_kernel() {
    extern __shared__ char sm[];
    const uint32_t smb = smem_u32(sm);
    const int tid  = threadIdx.x;
    const int lane = tid & 31;
    const int w    = tid >> 5;
    const int qt   = gridDim.y - 1 - blockIdx.y;   // LPT: biggest q-tiles first
    const int bh   = blockIdx.x;
    const int ntiles = 2 * qt + 2;

    {
        size_t qoff = ((size_t)bh * SEQ + (size_t)qt * FQ) * HDIM;
#pragma unroll
        for (int i = tid; i < 2048; i += 256) {
            int r = i >> 4, c = i & 15;
            cp16(smb + OQH + r * QROWB + c * 16, g_qhi + qoff + (size_t)r * HDIM + c * 8);
            cp16(smb + OQL + r * QROWB + c * 16, g_qlo + qoff + (size_t)r * HDIM + c * 8);
        }
    }

    auto load_kv = [&](int st, int kt) {
        uint32_t sb = smb + OST + st * FSTAGE;
        size_t koff = ((size_t)bh * SEQ + (size_t)kt * FK) * HDIM;
#pragma unroll
        for (int i = tid; i < 1024; i += 256) {
            int r = i >> 4, c = i & 15;
            cp16(sb + r * QROWB + c * 16,       g_khi + koff + (size_t)r * HDIM + c * 8);
            cp16(sb + FKL + r * QROWB + c * 16, g_klo + koff + (size_t)r * HDIM + c * 8);
        }
        size_t voff = (size_t)bh * HDIM * SEQ + (size_t)kt * FK;
#pragma unroll
        for (int i = tid; i < 1024; i += 256) {
            int d = i >> 3, c = i & 7;
            cp16(sb + FVH + d * VROWB + c * 16, g_vhi + voff + (size_t)d * SEQ + c * 8);
            cp16(sb + FVL + d * VROWB + c * 16, g_vlo + voff + (size_t)d * SEQ + c * 8);
        }
    };

    load_kv(0, 0);
    asm volatile("cp.async.commit_group;" ::: "memory");

    float o[16][4];
#pragma unroll
    for (int i = 0; i < 16; i++)
#pragma unroll
        for (int j = 0; j < 4; j++) o[i][j] = 0.f;
    float m0 = -CUDART_INF_F, m1 = -CUDART_INF_F, l0 = 0.f, l1 = 0.f;

    const int a_row = lane & 15;
    const int a_col = (lane >> 4) * 8;
    const int b_nl  = (lane & 7) + ((lane >> 4) & 1) * 8;
    const int b_kl  = ((lane >> 3) & 1) * 8;
    const int qrow0 = qt * FQ + w * 16 + (lane >> 2);

    for (int kt = 0; kt < ntiles; kt++) {
        if (kt + 1 < ntiles) load_kv((kt + 1) & 1, kt + 1);
        asm volatile("cp.async.commit_group;" ::: "memory");
        asm volatile("cp.async.wait_group 1;" ::: "memory");
        __syncthreads();

        const uint32_t kb = smb + OST + (kt & 1) * FSTAGE;
        const uint32_t vb = kb + FVH;

        float s[8][4];
#pragma unroll
        for (int i = 0; i < 8; i++)
#pragma unroll
            for (int j = 0; j < 4; j++) s[i][j] = 0.f;

#pragma unroll
        for (int ks = 0; ks < 8; ks++) {
            uint32_t qh[4], ql[4];
            uint32_t qaddr = smb + OQH + (uint32_t)((w * 16 + a_row) * QROWB + (ks * 16 + a_col) * 2);
            ldsm4(qh, qaddr);
            ldsm4(ql, qaddr + (OQL - OQH));
#pragma unroll
            for (int nt2 = 0; nt2 < 4; nt2++) {
                uint32_t kh[4], kl[4];
                uint32_t kaddr = kb + (uint32_t)((nt2 * 16 + b_nl) * QROWB + (ks * 16 + b_kl) * 2);
                ldsm4(kh, kaddr);
                ldsm4(kl, kaddr + FKL);
                mma_bf16(s[nt2 * 2],     qh, kh[0], kh[1]);
                mma_bf16(s[nt2 * 2 + 1], qh, kh[2], kh[3]);
                mma_bf16(s[nt2 * 2],     qh, kl[0], kl[1]);
                mma_bf16(s[nt2 * 2 + 1], qh, kl[2], kl[3]);
                mma_bf16(s[nt2 * 2],     ql, kh[0], kh[1]);
                mma_bf16(s[nt2 * 2 + 1], ql, kh[2], kh[3]);
            }
        }

        if (kt * FK + FK - 1 > qt * FQ + w * 16) {
#pragma unroll
            for (int nt = 0; nt < 8; nt++) {
                int key = kt * FK + nt * 8 + (lane & 3) * 2;
                if (key     > qrow0)     s[nt][0] = -CUDART_INF_F;
                if (key + 1 > qrow0)     s[nt][1] = -CUDART_INF_F;
                if (key     > qrow0 + 8) s[nt][2] = -CUDART_INF_F;
                if (key + 1 > qrow0 + 8) s[nt][3] = -CUDART_INF_F;
            }
        }

        float mx0 = -CUDART_INF_F, mx1 = -CUDART_INF_F;
#pragma unroll
        for (int nt = 0; nt < 8; nt++) {
            mx0 = fmaxf(mx0, fmaxf(s[nt][0], s[nt][1]));
            mx1 = fmaxf(mx1, fmaxf(s[nt][2], s[nt][3]));
        }
        mx0 = fmaxf(mx0, __shfl_xor_sync(0xffffffffu, mx0, 1));
        mx0 = fmaxf(mx0, __shfl_xor_sync(0xffffffffu, mx0, 2));
        mx1 = fmaxf(mx1, __shfl_xor_sync(0xffffffffu, mx1, 1));
        mx1 = fmaxf(mx1, __shfl_xor_sync(0xffffffffu, mx1, 2));
        float mn0 = fmaxf(m0, mx0), mn1 = fmaxf(m1, mx1);
        float al0 = exp2p(m0 - mn0), al1 = exp2p(m1 - mn1);
        m0 = mn0; m1 = mn1;

        float sum0 = 0.f, sum1 = 0.f;
#pragma unroll
        for (int nt = 0; nt < 8; nt++) {
            s[nt][0] = exp2p(s[nt][0] - mn0); sum0 += s[nt][0];
            s[nt][1] = exp2p(s[nt][1] - mn0); sum0 += s[nt][1];
            s[nt][2] = exp2p(s[nt][2] - mn1); sum1 += s[nt][2];
            s[nt][3] = exp2p(s[nt][3] - mn1); sum1 += s[nt][3];
        }
        // deferred l-reduction: per-thread quarter-row partials
        l0 = l0 * al0 + sum0;
        l1 = l1 * al1 + sum1;

#pragma unroll
        for (int nt = 0; nt < 16; nt++) {
            o[nt][0] *= al0; o[nt][1] *= al0;
            o[nt][2] *= al1; o[nt][3] *= al1;
        }

#pragma unroll
        for (int g = 0; g < 4; g++) {
            float h00 = __bfloat162float(__float2bfloat16(s[2*g][0]));
            float h01 = __bfloat162float(__float2bfloat16(s[2*g][1]));
            float h02 = __bfloat162float(__float2bfloat16(s[2*g][2]));
            float h03 = __bfloat162float(__float2bfloat16(s[2*g][3]));
            float h10 = __bfloat162float(__float2bfloat16(s[2*g+1][0]));
            float h11 = __bfloat162float(__float2bfloat16(s[2*g+1][1]));
            float h12 = __bfloat162float(__float2bfloat16(s[2*g+1][2]));
            float h13 = __bfloat162float(__float2bfloat16(s[2*g+1][3]));
            uint32_t phi[4], plo[4];
            phi[0] = pack_bf16(h00, h01);
            phi[1] = pack_bf16(h02, h03);
            phi[2] = pack_bf16(h10, h11);
            phi[3] = pack_bf16(h12, h13);
            plo[0] = pack_bf16(s[2*g][0] - h00,   s[2*g][1] - h01);
            plo[1] = pack_bf16(s[2*g][2] - h02,   s[2*g][3] - h03);
            plo[2] = pack_bf16(s[2*g+1][0] - h10, s[2*g+1][1] - h11);
            plo[3] = pack_bf16(s[2*g+1][2] - h12, s[2*g+1][3] - h13);

#pragma unroll
            for (int dt2 = 0; dt2 < 8; dt2++) {
                uint32_t vh[4], vl[4];
                uint32_t vaddr = vb + (uint32_t)((dt2 * 16 + b_nl) * VROWB + (g * 16 + b_kl) * 2);
                ldsm4(vh, vaddr);
                ldsm4(vl, vaddr + (FVL - FVH));
                mma_bf16(o[dt2 * 2],     phi, vh[0], vh[1]);
                mma_bf16(o[dt2 * 2 + 1], phi, vh[2], vh[3]);
                mma_bf16(o[dt2 * 2],     phi, vl[0], vl[1]);
                mma_bf16(o[dt2 * 2 + 1], phi, vl[2], vl[3]);
                mma_bf16(o[dt2 * 2],     plo, vh[0], vh[1]);
                mma_bf16(o[dt2 * 2 + 1], plo, vh[2], vh[3]);
            }
        }
        __syncthreads();
    }

    // ---- deferred cross-thread l reduction ----
    l0 += __shfl_xor_sync(0xffffffffu, l0, 1);
    l0 += __shfl_xor_sync(0xffffffffu, l0, 2);
    l1 += __shfl_xor_sync(0xffffffffu, l1, 1);
    l1 += __shfl_xor_sync(0xffffffffu, l1, 2);

    // ---- epilogue: write bf16 [Ahi|Ahi|Alo] A-operand rows into g_A2 ----
    const float invl0 = 1.0f / l0;
    const float invl1 = 1.0f / l1;
    const int b = bh >> 5, h = bh & 31;
    const size_t r0 = (size_t)(b * SEQ + qt * FQ + w * 16 + (lane >> 2));
#pragma unroll
    for (int nt = 0; nt < 16; nt++) {
        size_t cbase = (size_t)h * HDIM + nt * 8 + (lane & 3) * 2;
        float x0 = o[nt][0] * invl0, x1 = o[nt][1] * invl0;
        float x2 = o[nt][2] * invl1, x3 = o[nt][3] * invl1;

        float h0 = __bfloat162float(__float2bfloat16(x0));
        float h1 = __bfloat162float(__float2bfloat16(x1));
        float h2 = __bfloat162float(__float2bfloat16(x2));
        float h3 = __bfloat162float(__float2bfloat16(x3));
        uint32_t hi01 = pack_bf16(x0, x1);
        uint32_t lo01 = pack_bf16(x0 - h0, x1 - h1);
        uint32_t hi23 = pack_bf16(x2, x3);
        uint32_t lo23 = pack_bf16(x2 - h2, x3 - h3);

        __nv_bfloat16* a0 = &g_A2[r0 * KSPLIT + cbase];
        __nv_bfloat16* a1 = &g_A2[(r0 + 8) * KSPLIT + cbase];
        *(uint32_t*)(a0)        = hi01;
        *(uint32_t*)(a0 + 4096) = hi01;
        *(uint32_t*)(a0 + 8192) = lo01;
        *(uint32_t*)(a1)        = hi23;
        *(uint32_t*)(a1 + 4096) = hi23;
        *(uint32_t*)(a1 + 8192) = lo23;
    }
}

// ============================================================================
extern "C" void kernel_launch(void* const* d_in, const int* in_sizes, int n_in,
                              void* d_out, int out_size) {
    const float* hidden    = (const float*)d_in[0];
    const int*   positions = (const int*)d_in[1];
    const float* Wqkv      = (const float*)d_in[2];
    const float* Wout      = (const float*)d_in[3];
    float*       out       = (float*)d_out;

    float*         qkv; cudaGetSymbolAddress((void**)&qkv, g_qkv);
    __nv_bfloat16* A2;  cudaGetSymbolAddress((void**)&A2,  g_A2);
    __nv_bfloat16* B2;  cudaGetSymbolAddress((void**)&B2,  g_B2);

    static bool attr_done = false;
    if (!attr_done) {
        cudaFuncSetAttribute(gemm_bf16_kernel, cudaFuncAttributeMaxDynamicSharedMemorySize, GSMEM_B);
        cudaFuncSetAttribute(flash_tc_kernel, cudaFuncAttributeMaxDynamicSharedMemorySize, FSMEM);
        attr_done = true;
    }

    // 1) split hidden -> A2, Wqkv -> B2 (bf16 3-term) ; rope table
    split_act_kernel<<<(MROWS * (HID / 4)) / 256, 256>>>(hidden, A2);
    split_w_kernel<<<dim3(QKVN / 32, HID / 32), 256>>>(Wqkv, B2, QKVN);
    rope_tab_kernel<<<(MROWS * 32) / 256, 256>>>(positions);

    // 2) QKV projection with FUSED rope + q/k split in the epilogue (mode 1)
    gemm_bf16_kernel<<<dim3(QKVN / 128, MROWS / 128), 128, GSMEM_B>>>(A2, B2, qkv, QKVN, 1);

    // 3) split v (transposed)
    split_v_kernel<<<dim3(SEQ / 32, HDIM / 32, BATCH * NH), 256>>>();

    // 4) tensor-core causal flash attention — LPT grid: x=bh, y=qt index
    flash_tc_kernel<<<dim3(BATCH * NH, SEQ / FQ), 256, FSMEM>>>();

    // 5) output projection (mode 0)
    split_w_kernel<<<dim3(HID / 32, HID / 32), 256>>>(Wout, B2, HID);
    gemm_bf16_kernel<<<dim3(HID / 128, MROWS / 128), 128, GSMEM_B>>>(A2, B2, out, HID, 0);
}